// round 10
// baseline (speedup 1.0000x reference)
#include <cuda_runtime.h>
#include <cuda_fp16.h>

#define W    512
#define NIMG 32
#define CH   4
#define PW   768   // padded pairs width: biased index range [22, 744] fits

// Scratch: filtered projections transposed to [n][angle][r]
__device__ __align__(16) float g_proj[(size_t)NIMG * W * W];
// Ramp-filter spatial taps, rearranged: g_hh[i] = h[(i-511) mod 1024], i in [0,1022]
__device__ float g_hh[1024];
// Per-angle (cos*255.5, sin*255.5)
__device__ float2 g_cs[W];

// ---------------------------------------------------------------------------
// K0: taps. h[m] = (1/1024) * sum_k filt[k] * cos(2*pi*k*m/1024),
// filt[k] = min(k,1024-k)/512. One block per tap, 256-thread double reduction.
// ---------------------------------------------------------------------------
__global__ __launch_bounds__(256) void k_hh() {
    __shared__ double red[256];
    const int i = blockIdx.x;
    const int t = threadIdx.x;
    if (i == 1023) { if (t == 0) g_hh[1023] = 0.0f; return; }
    const int m2 = (i + 513) & 1023;              // (i-511) mod 1024
    double s = 0.0;
    for (int k = t; k < 1024; k += 256) {
        int mn = (k < 512) ? k : (1024 - k);
        float f = (float)mn * (1.0f / 512.0f);    // filt[k]
        int ph = (k * m2) & 1023;                 // exact integer phase
        s += (double)f * (double)cospif((float)ph * (1.0f / 512.0f));
    }
    red[t] = s;
    __syncthreads();
    for (int st = 128; st > 0; st >>= 1) {
        if (t < st) red[t] += red[t + st];
        __syncthreads();
    }
    if (t == 0) g_hh[i] = (float)(red[0] / 1024.0);
}

__global__ void k_trig(const float* __restrict__ theta) {
    int l = threadIdx.x;
    if (l < W) {
        float frac = theta[l] * (1.0f / 180.0f);
        g_cs[l] = make_float2(cospif(frac) * 255.5f, sinpif(frac) * 255.5f);
    }
}

// ---------------------------------------------------------------------------
// K1: ramp filter as Toeplitz GEMM, output transposed:
//   g_proj[n][l][r] = sum_{m=0}^{511} x[n][m][l] * hh[r - m + 511]
// 256 threads, tile 128 l x 128 r, micro-tile 8l x 8r, packed fma.rn.f32x2.
// ---------------------------------------------------------------------------
__global__ __launch_bounds__(256) void k_filter(const float* __restrict__ x) {
    __shared__ __align__(16) float2 hh2[1023];  // hh2[i] = (hh[i], hh[i+1])
    __shared__ __align__(16) float  As[16][128];
    const int tid = threadIdx.x;
    const int n     = blockIdx.z;
    const int rBase = blockIdx.x * 128;
    const int lBase = blockIdx.y * 128;

    for (int i = tid; i < 1023; i += 256)
        hh2[i] = make_float2(g_hh[i], g_hh[i + 1]);

    const int tx = tid & 15;          // l lane (strided by 16)
    const int ty = tid >> 4;          // r group (8 consecutive r)
    const int r0 = rBase + ty * 8;

    unsigned long long acc[8][4];     // [sl][pair]: pair p = (r0+2p, r0+2p+1)
#pragma unroll
    for (int sl = 0; sl < 8; ++sl)
#pragma unroll
        for (int p = 0; p < 4; ++p) acc[sl][p] = 0ull;

    const float* xn = x + (size_t)n * W * W;
    const int lrow = tid >> 5;        // 0..7
    const int c4   = (tid & 31) << 2; // 0..124

    for (int mc = 0; mc < 32; ++mc) {
        __syncthreads();
        const float* src = xn + (size_t)(mc * 16) * W + lBase;
        *(float4*)&As[lrow][c4]     = *(const float4*)(src + (size_t)lrow * W + c4);
        *(float4*)&As[lrow + 8][c4] = *(const float4*)(src + (size_t)(lrow + 8) * W + c4);
        __syncthreads();
#pragma unroll
        for (int mm = 0; mm < 16; ++mm) {
            const int hb = 511 + r0 - (mc * 16 + mm);
            unsigned long long h2[4];
#pragma unroll
            for (int p = 0; p < 4; ++p)
                h2[p] = *(const unsigned long long*)(&hh2[hb + 2 * p]);
#pragma unroll
            for (int sl = 0; sl < 8; ++sl) {
                float a = As[mm][tx + 16 * sl];
                unsigned long long a2;
                asm("mov.b64 %0, {%1, %1};" : "=l"(a2) : "r"(__float_as_uint(a)));
#pragma unroll
                for (int p = 0; p < 4; ++p)
                    asm("fma.rn.f32x2 %0, %1, %2, %0;"
                        : "+l"(acc[sl][p]) : "l"(a2), "l"(h2[p]));
            }
        }
    }

#pragma unroll
    for (int sl = 0; sl < 8; ++sl) {
        const int l = lBase + tx + 16 * sl;
        float v[8];
#pragma unroll
        for (int p = 0; p < 4; ++p) {
            unsigned int lo, hi;
            asm("mov.b64 {%0, %1}, %2;" : "=r"(lo), "=r"(hi) : "l"(acc[sl][p]));
            v[2 * p]     = __uint_as_float(lo);
            v[2 * p + 1] = __uint_as_float(hi);
        }
        float* dst = g_proj + ((size_t)n * W + l) * W + r0;
        *(float4*)dst       = make_float4(v[0], v[1], v[2], v[3]);
        *(float4*)(dst + 4) = make_float4(v[4], v[5], v[6], v[7]);
    }
}

// ---------------------------------------------------------------------------
// K2: backprojection, 2 images per block. Block = 512 threads = 16 rows x 32
// lanes; thread owns 16 pixels (j = lane + 32u) in BOTH images. The lookup
// index is image-independent, so one LDS.64 fetches fp16 (p0,d) pairs for
// both images: 4 B/image/lookup -> crossbar floor halved.
//   v = p0 + frac*d, frac from 2^23 magic (RM), byte offset from 2^20 magic.
// Biased coordinate ryb = ry + 128 in [22,745]; guard entries are zero and
// only out-of-circle pixels (later masked) can land there.
// ---------------------------------------------------------------------------
__global__ __launch_bounds__(512, 2) void k_backproj(float* __restrict__ out) {
    __shared__ __align__(16) float raw[2][CH][W];
    __shared__ __align__(16) uint2 pairs[CH][PW];   // {half2(p0a,da), half2(p0b,db)}
    const int tid  = threadIdx.x;
    const int n0   = blockIdx.y * 2;
    const int i    = blockIdx.x * 16 + (tid >> 5);
    const int lane = tid & 31;
    const float STEP = 2.0f / 511.0f;
    const float ti   = fmaf((float)i, STEP, -1.0f);
    const float tj0  = fmaf((float)lane, STEP, -1.0f);

    // Zero whole pair table once; guards ([0,128) and [640,768)) stay zero.
    {
        uint2* pz = &pairs[0][0];
#pragma unroll
        for (int v = 0; v < (CH * PW) / 512; ++v)
            pz[tid + v * 512] = make_uint2(0u, 0u);
    }

    float acc0[16], acc1[16];
#pragma unroll
    for (int u = 0; u < 16; ++u) { acc0[u] = 0.0f; acc1[u] = 0.0f; }

    const float* pn0 = g_proj + (size_t)n0 * W * W;
    const float* pn1 = pn0 + (size_t)W * W;
    const char*  pbase = (const char*)&pairs[0][0];

    for (int lc = 0; lc < W / CH; ++lc) {
        __syncthreads();
        // stage CH angle rows for both images: CH*W/4 = 512 float4 each
        ((float4*)&raw[0][0][0])[tid] = ((const float4*)(pn0 + (size_t)lc * CH * W))[tid];
        ((float4*)&raw[1][0][0])[tid] = ((const float4*)(pn1 + (size_t)lc * CH * W))[tid];
        __syncthreads();
        // build fp16 pair table
#pragma unroll
        for (int v = 0; v < (CH * W) / 512; ++v) {
            int e = tid + v * 512;
            int l = e >> 9;
            int k = e & (W - 1);
            float pa = raw[0][l][k];
            float pb = raw[1][l][k];
            float da = (k < W - 1) ? (raw[0][l][k + 1] - pa) : 0.0f;
            float db = (k < W - 1) ? (raw[1][l][k + 1] - pb) : 0.0f;
            __half2 ha = __floats2half2_rn(pa, da);
            __half2 hb = __floats2half2_rn(pb, db);
            pairs[l][k + 128] = make_uint2(*reinterpret_cast<unsigned*>(&ha),
                                           *reinterpret_cast<unsigned*>(&hb));
        }
        __syncthreads();
#pragma unroll
        for (int a8 = 0; a8 < CH; ++a8) {
            const float2 cs   = g_cs[lc * CH + a8];
            const float  cB   = cs.x;
            const float  rowB = fmaf(-ti, cs.y, 383.5f);       // 255.5 + 128 bias
            const float  ry0  = fmaf(tj0, cB, rowB);
            const float  ust  = cB * (32.0f * STEP);
#pragma unroll
            for (int u = 0; u < 16; ++u) {
                float ryb = fmaf((float)u, ust, ry0);
                float b20, b23;
                asm("add.rm.f32 %0, %1, 0f49800000;" : "=f"(b20) : "f"(ryb)); // +2^20
                asm("add.rm.f32 %0, %1, 0f4B000000;" : "=f"(b23) : "f"(ryb)); // +2^23
                unsigned off = __float_as_uint(b20) & 0x1FF8u;  // 8*floor(ryb)
                float fl   = b23 - 8388608.0f;                  // floor(ryb), exact
                float frac = ryb - fl;
                uint2 w = *(const uint2*)(pbase + (a8 * (PW * 8)) + off);
                float2 A = __half22float2(*reinterpret_cast<__half2*>(&w.x));
                float2 B = __half22float2(*reinterpret_cast<__half2*>(&w.y));
                acc0[u] = fmaf(frac, A.y, acc0[u] + A.x);
                acc1[u] = fmaf(frac, B.y, acc1[u] + B.x);
            }
        }
    }

    const float scale = (float)(3.14159265358979323846 / 1024.0); // pi/(2L)
    const float ti2 = ti * ti;
    float* orow0 = out + ((size_t)n0 * W + i) * W;
    float* orow1 = orow0 + (size_t)W * W;
#pragma unroll
    for (int u = 0; u < 16; ++u) {
        float tj = fmaf((float)(lane + 32 * u), STEP, -1.0f);
        bool in = (ti2 + tj * tj <= 1.0f);
        orow0[lane + 32 * u] = in ? acc0[u] * scale : 0.0f;
        orow1[lane + 32 * u] = in ? acc1[u] * scale : 0.0f;
    }
}

extern "C" void kernel_launch(void* const* d_in, const int* in_sizes, int n_in,
                              void* d_out, int out_size) {
    const float* x     = (const float*)d_in[0];
    const float* theta = (const float*)d_in[1];
    if (n_in >= 2 && in_sizes[0] == W && in_sizes[1] != W) { // defensive order swap
        x = (const float*)d_in[1];
        theta = (const float*)d_in[0];
    }
    float* out = (float*)d_out;

    k_hh<<<1024, 256>>>();
    k_trig<<<1, 512>>>(theta);

    dim3 g1(4, 4, NIMG);
    k_filter<<<g1, 256>>>(x);

    dim3 g2(32, NIMG / 2);
    k_backproj<<<g2, 512>>>(out);
}

// round 11
// speedup vs baseline: 1.1081x; 1.1081x over previous
#include <cuda_runtime.h>
#include <cuda_fp16.h>

#define W    512
#define NIMG 32
#define CH   4

// Scratch: filtered projections transposed to [n][angle][r]
__device__ __align__(16) float g_proj[(size_t)NIMG * W * W];
// Ramp-filter spatial taps, rearranged: g_hh[i] = h[(i-511) mod 1024], i in [0,1022]
__device__ float g_hh[1024];
// Per-angle (cos*255.5, sin*255.5)
__device__ float2 g_cs[W];

// ---------------------------------------------------------------------------
// K0: taps. h[m] = (1/1024) * sum_k filt[k] * cos(2*pi*k*m/1024),
// filt[k] = min(k,1024-k)/512. One block per tap, 256-thread double reduction.
// ---------------------------------------------------------------------------
__global__ __launch_bounds__(256) void k_hh() {
    __shared__ double red[256];
    const int i = blockIdx.x;
    const int t = threadIdx.x;
    if (i == 1023) { if (t == 0) g_hh[1023] = 0.0f; return; }
    const int m2 = (i + 513) & 1023;              // (i-511) mod 1024
    double s = 0.0;
    for (int k = t; k < 1024; k += 256) {
        int mn = (k < 512) ? k : (1024 - k);
        float f = (float)mn * (1.0f / 512.0f);    // filt[k]
        int ph = (k * m2) & 1023;                 // exact integer phase
        s += (double)f * (double)cospif((float)ph * (1.0f / 512.0f));
    }
    red[t] = s;
    __syncthreads();
    for (int st = 128; st > 0; st >>= 1) {
        if (t < st) red[t] += red[t + st];
        __syncthreads();
    }
    if (t == 0) g_hh[i] = (float)(red[0] / 1024.0);
}

__global__ void k_trig(const float* __restrict__ theta) {
    int l = threadIdx.x;
    if (l < W) {
        float frac = theta[l] * (1.0f / 180.0f);
        g_cs[l] = make_float2(cospif(frac) * 255.5f, sinpif(frac) * 255.5f);
    }
}

// ---------------------------------------------------------------------------
// K1: ramp filter as Toeplitz GEMM, output transposed:
//   g_proj[n][l][r] = sum_{m=0}^{511} x[n][m][l] * hh[r - m + 511]
// 256 threads, tile 128 l x 128 r, micro-tile 8l x 8r, packed fma.rn.f32x2.
// ---------------------------------------------------------------------------
__global__ __launch_bounds__(256) void k_filter(const float* __restrict__ x) {
    __shared__ __align__(16) float2 hh2[1023];  // hh2[i] = (hh[i], hh[i+1])
    __shared__ __align__(16) float  As[16][128];
    const int tid = threadIdx.x;
    const int n     = blockIdx.z;
    const int rBase = blockIdx.x * 128;
    const int lBase = blockIdx.y * 128;

    for (int i = tid; i < 1023; i += 256)
        hh2[i] = make_float2(g_hh[i], g_hh[i + 1]);

    const int tx = tid & 15;          // l lane (strided by 16)
    const int ty = tid >> 4;          // r group (8 consecutive r)
    const int r0 = rBase + ty * 8;

    unsigned long long acc[8][4];     // [sl][pair]: pair p = (r0+2p, r0+2p+1)
#pragma unroll
    for (int sl = 0; sl < 8; ++sl)
#pragma unroll
        for (int p = 0; p < 4; ++p) acc[sl][p] = 0ull;

    const float* xn = x + (size_t)n * W * W;
    const int lrow = tid >> 5;        // 0..7
    const int c4   = (tid & 31) << 2; // 0..124

    for (int mc = 0; mc < 32; ++mc) {
        __syncthreads();
        const float* src = xn + (size_t)(mc * 16) * W + lBase;
        *(float4*)&As[lrow][c4]     = *(const float4*)(src + (size_t)lrow * W + c4);
        *(float4*)&As[lrow + 8][c4] = *(const float4*)(src + (size_t)(lrow + 8) * W + c4);
        __syncthreads();
#pragma unroll
        for (int mm = 0; mm < 16; ++mm) {
            const int hb = 511 + r0 - (mc * 16 + mm);
            unsigned long long h2[4];
#pragma unroll
            for (int p = 0; p < 4; ++p)
                h2[p] = *(const unsigned long long*)(&hh2[hb + 2 * p]);
#pragma unroll
            for (int sl = 0; sl < 8; ++sl) {
                float a = As[mm][tx + 16 * sl];
                unsigned long long a2;
                asm("mov.b64 %0, {%1, %1};" : "=l"(a2) : "r"(__float_as_uint(a)));
#pragma unroll
                for (int p = 0; p < 4; ++p)
                    asm("fma.rn.f32x2 %0, %1, %2, %0;"
                        : "+l"(acc[sl][p]) : "l"(a2), "l"(h2[p]));
            }
        }
    }

#pragma unroll
    for (int sl = 0; sl < 8; ++sl) {
        const int l = lBase + tx + 16 * sl;
        float v[8];
#pragma unroll
        for (int p = 0; p < 4; ++p) {
            unsigned int lo, hi;
            asm("mov.b64 {%0, %1}, %2;" : "=r"(lo), "=r"(hi) : "l"(acc[sl][p]));
            v[2 * p]     = __uint_as_float(lo);
            v[2 * p + 1] = __uint_as_float(hi);
        }
        float* dst = g_proj + ((size_t)n * W + l) * W + r0;
        *(float4*)dst       = make_float4(v[0], v[1], v[2], v[3]);
        *(float4*)(dst + 4) = make_float4(v[4], v[5], v[6], v[7]);
    }
}

// pack two fp32 into half2 (lo in low half, hi in high half): 1 instr (F2FP)
__device__ __forceinline__ unsigned pack_f16x2(float lo, float hi) {
    unsigned r;
    asm("cvt.rn.f16x2.f32 %0, %2, %1;" : "=r"(r) : "f"(lo), "f"(hi));
    return r;
}

// ---------------------------------------------------------------------------
// K2: backprojection, 4 images per block. Block = 512 thr = 16 rows x 32
// lanes; thread owns 8 pixels (j = ch*256 + lane + 32u) of 4 images.
// Pair tables (fp16): pairsA[l][k] = {h2(p_i0,p_i1), h2(d_i0,d_i1)},
// pairsB for images 2,3. One (index, frac) serves all 4 images:
//   2x LDS.64 + 2x HFMA2 lerp + 4x (F2F + FADD) fp32 accumulate.
// In-circle pixels have ry in (0,511) with margin >= 4.9e-4 (lattice/circle
// arithmetic), so no clamps: the 2^20 magic's "& 0xFF8" extracts
// floor(ry)*8 AND wraps out-of-circle garbage in-bounds (masked at the end).
// ---------------------------------------------------------------------------
__global__ __launch_bounds__(512, 2) void k_backproj(float* __restrict__ out) {
    __shared__ __align__(16) uint2 pairsA[CH][W];   // imgs 0,1
    __shared__ __align__(16) uint2 pairsB[CH][W];   // imgs 2,3
    const int tid  = threadIdx.x;
    const int rg   = blockIdx.x >> 1;       // row group (0..31)
    const int chh  = blockIdx.x & 1;        // column half
    const int n0   = blockIdx.y * 4;
    const int i    = rg * 16 + (tid >> 5);
    const int lane = tid & 31;
    const float STEP = 2.0f / 511.0f;
    const float ti   = fmaf((float)i, STEP, -1.0f);
    const float tj0  = fmaf((float)(chh * 256 + lane), STEP, -1.0f);
    const float UST0 = 32.0f * STEP;

    // build-role indices: angle row l, strided k = c + 128t
    const int bl = tid >> 7;                 // 0..3
    const int bc = tid & 127;                // 0..127

    float acc[4][8];
#pragma unroll
    for (int m = 0; m < 4; ++m)
#pragma unroll
        for (int u = 0; u < 8; ++u) acc[m][u] = 0.0f;

    const float* gbase = g_proj + (size_t)n0 * W * W;

    for (int lc = 0; lc < W / CH; ++lc) {
        // prefetch trig for this chunk's 4 angles
        float4 csA = *(const float4*)&g_cs[lc * CH];      // c0,s0,c1,s1
        float4 csB = *(const float4*)&g_cs[lc * CH + 2];  // c2,s2,c3,s3

        __syncthreads();
        // build fp16 pair tables straight from L2 (no staging array)
        {
            const float* rowp = gbase + ((size_t)(lc * CH + bl)) * W;
#pragma unroll
            for (int t = 0; t < 4; ++t) {
                int k = bc + 128 * t;
                int kn = (k < W - 1) ? (k + 1) : k;   // k=511 -> d=0
                float p0 = rowp[k];
                float p1 = rowp[k +     W * W];
                float p2 = rowp[k + 2 * W * W];
                float p3 = rowp[k + 3 * W * W];
                float d0 = rowp[kn]             - p0;
                float d1 = rowp[kn +     W * W] - p1;
                float d2 = rowp[kn + 2 * W * W] - p2;
                float d3 = rowp[kn + 3 * W * W] - p3;
                pairsA[bl][k] = make_uint2(pack_f16x2(p0, p1), pack_f16x2(d0, d1));
                pairsB[bl][k] = make_uint2(pack_f16x2(p2, p3), pack_f16x2(d2, d3));
            }
        }
        __syncthreads();

#pragma unroll
        for (int a = 0; a < CH; ++a) {
            const float cB = (a == 0) ? csA.x : (a == 1) ? csA.z : (a == 2) ? csB.x : csB.z;
            const float sB = (a == 0) ? csA.y : (a == 1) ? csA.w : (a == 2) ? csB.y : csB.w;
            const float rowB = fmaf(-ti, sB, 255.5f);
            const float ry0  = fmaf(tj0, cB, rowB);
            const float ust  = cB * UST0;
            const char* PA = (const char*)&pairsA[a][0];
            const char* PB = (const char*)&pairsB[a][0];
#pragma unroll
            for (int u = 0; u < 8; ++u) {
                float ry = fmaf((float)u, ust, ry0);
                float b20, b23;
                asm("add.rm.f32 %0, %1, 0f49800000;" : "=f"(b20) : "f"(ry)); // +2^20
                asm("add.rm.f32 %0, %1, 0f4B000000;" : "=f"(b23) : "f"(ry)); // +2^23
                unsigned off = __float_as_uint(b20) & 0xFF8u;   // 8*floor(ry), wraps
                float fl   = b23 - 8388608.0f;                  // floor(ry)
                float frac = ry - fl;
                unsigned fr2 = pack_f16x2(frac, frac);
                uint2 wA = *(const uint2*)(PA + off);
                uint2 wB = *(const uint2*)(PB + off);
                __half2 hf  = *reinterpret_cast<__half2*>(&fr2);
                __half2 v01 = __hfma2(hf, *reinterpret_cast<__half2*>(&wA.y),
                                          *reinterpret_cast<__half2*>(&wA.x));
                __half2 v23 = __hfma2(hf, *reinterpret_cast<__half2*>(&wB.y),
                                          *reinterpret_cast<__half2*>(&wB.x));
                acc[0][u] += __low2float(v01);
                acc[1][u] += __high2float(v01);
                acc[2][u] += __low2float(v23);
                acc[3][u] += __high2float(v23);
            }
        }
    }

    const float scale = (float)(3.14159265358979323846 / 1024.0); // pi/(2L)
    const float ti2 = ti * ti;
#pragma unroll
    for (int u = 0; u < 8; ++u) {
        int j = chh * 256 + lane + 32 * u;
        float tj = fmaf((float)j, STEP, -1.0f);
        bool in = (ti2 + tj * tj <= 1.0f);
        float* po = out + ((size_t)n0 * W + i) * W + j;
#pragma unroll
        for (int m = 0; m < 4; ++m)
            po[(size_t)m * W * W] = in ? acc[m][u] * scale : 0.0f;
    }
}

extern "C" void kernel_launch(void* const* d_in, const int* in_sizes, int n_in,
                              void* d_out, int out_size) {
    const float* x     = (const float*)d_in[0];
    const float* theta = (const float*)d_in[1];
    if (n_in >= 2 && in_sizes[0] == W && in_sizes[1] != W) { // defensive order swap
        x = (const float*)d_in[1];
        theta = (const float*)d_in[0];
    }
    float* out = (float*)d_out;

    k_hh<<<1024, 256>>>();
    k_trig<<<1, 512>>>(theta);

    dim3 g1(4, 4, NIMG);
    k_filter<<<g1, 256>>>(x);

    dim3 g2(64, NIMG / 4);
    k_backproj<<<g2, 512>>>(out);
}

// round 12
// speedup vs baseline: 1.3430x; 1.2120x over previous
#include <cuda_runtime.h>
#include <cuda_fp16.h>

#define W      512
#define NIMG   32
#define CH     4
#define NGRP   (NIMG / 4)      // 8 image groups
#define CHUNKS (W / CH)        // 128 angle chunks
#define CHUNK_U2 4096          // uint2 entries per chunk: 4 angles x 2 tabs x 512
#define NBUF   3

// Scratch: filtered projections transposed to [n][angle][r]
__device__ __align__(16) float g_proj[(size_t)NIMG * W * W];
// Packed fp16 pair tables: [group][chunk][angle-in-chunk][tab][k]
//   tab 0: {h2(p_img0,p_img1), h2(d_img0,d_img1)}, tab 1: imgs 2,3
__device__ __align__(16) uint2 g_pairs[(size_t)NGRP * CHUNKS * CHUNK_U2];
// Ramp-filter spatial taps, rearranged: g_hh[i] = h[(i-511) mod 1024]
__device__ float g_hh[1024];
// Per-angle (cos*255.5, sin*255.5)
__device__ float2 g_cs[W];

// ---------------------------------------------------------------------------
// K0: taps. h[m] = (1/1024) * sum_k filt[k] * cos(2*pi*k*m/1024),
// filt[k] = min(k,1024-k)/512. One block per tap, 256-thread double reduction.
// ---------------------------------------------------------------------------
__global__ __launch_bounds__(256) void k_hh() {
    __shared__ double red[256];
    const int i = blockIdx.x;
    const int t = threadIdx.x;
    if (i == 1023) { if (t == 0) g_hh[1023] = 0.0f; return; }
    const int m2 = (i + 513) & 1023;              // (i-511) mod 1024
    double s = 0.0;
    for (int k = t; k < 1024; k += 256) {
        int mn = (k < 512) ? k : (1024 - k);
        float f = (float)mn * (1.0f / 512.0f);    // filt[k]
        int ph = (k * m2) & 1023;                 // exact integer phase
        s += (double)f * (double)cospif((float)ph * (1.0f / 512.0f));
    }
    red[t] = s;
    __syncthreads();
    for (int st = 128; st > 0; st >>= 1) {
        if (t < st) red[t] += red[t + st];
        __syncthreads();
    }
    if (t == 0) g_hh[i] = (float)(red[0] / 1024.0);
}

__global__ void k_trig(const float* __restrict__ theta) {
    int l = threadIdx.x;
    if (l < W) {
        float frac = theta[l] * (1.0f / 180.0f);
        g_cs[l] = make_float2(cospif(frac) * 255.5f, sinpif(frac) * 255.5f);
    }
}

// ---------------------------------------------------------------------------
// K1: ramp filter as Toeplitz GEMM, output transposed:
//   g_proj[n][l][r] = sum_{m=0}^{511} x[n][m][l] * hh[r - m + 511]
// 256 threads, tile 128 l x 128 r, micro-tile 8l x 8r, packed fma.rn.f32x2.
// ---------------------------------------------------------------------------
__global__ __launch_bounds__(256) void k_filter(const float* __restrict__ x) {
    __shared__ __align__(16) float2 hh2[1023];  // hh2[i] = (hh[i], hh[i+1])
    __shared__ __align__(16) float  As[16][128];
    const int tid = threadIdx.x;
    const int n     = blockIdx.z;
    const int rBase = blockIdx.x * 128;
    const int lBase = blockIdx.y * 128;

    for (int i = tid; i < 1023; i += 256)
        hh2[i] = make_float2(g_hh[i], g_hh[i + 1]);

    const int tx = tid & 15;          // l lane (strided by 16)
    const int ty = tid >> 4;          // r group (8 consecutive r)
    const int r0 = rBase + ty * 8;

    unsigned long long acc[8][4];     // [sl][pair]: pair p = (r0+2p, r0+2p+1)
#pragma unroll
    for (int sl = 0; sl < 8; ++sl)
#pragma unroll
        for (int p = 0; p < 4; ++p) acc[sl][p] = 0ull;

    const float* xn = x + (size_t)n * W * W;
    const int lrow = tid >> 5;        // 0..7
    const int c4   = (tid & 31) << 2; // 0..124

    for (int mc = 0; mc < 32; ++mc) {
        __syncthreads();
        const float* src = xn + (size_t)(mc * 16) * W + lBase;
        *(float4*)&As[lrow][c4]     = *(const float4*)(src + (size_t)lrow * W + c4);
        *(float4*)&As[lrow + 8][c4] = *(const float4*)(src + (size_t)(lrow + 8) * W + c4);
        __syncthreads();
#pragma unroll
        for (int mm = 0; mm < 16; ++mm) {
            const int hb = 511 + r0 - (mc * 16 + mm);
            unsigned long long h2[4];
#pragma unroll
            for (int p = 0; p < 4; ++p)
                h2[p] = *(const unsigned long long*)(&hh2[hb + 2 * p]);
#pragma unroll
            for (int sl = 0; sl < 8; ++sl) {
                float a = As[mm][tx + 16 * sl];
                unsigned long long a2;
                asm("mov.b64 %0, {%1, %1};" : "=l"(a2) : "r"(__float_as_uint(a)));
#pragma unroll
                for (int p = 0; p < 4; ++p)
                    asm("fma.rn.f32x2 %0, %1, %2, %0;"
                        : "+l"(acc[sl][p]) : "l"(a2), "l"(h2[p]));
            }
        }
    }

#pragma unroll
    for (int sl = 0; sl < 8; ++sl) {
        const int l = lBase + tx + 16 * sl;
        float v[8];
#pragma unroll
        for (int p = 0; p < 4; ++p) {
            unsigned int lo, hi;
            asm("mov.b64 {%0, %1}, %2;" : "=r"(lo), "=r"(hi) : "l"(acc[sl][p]));
            v[2 * p]     = __uint_as_float(lo);
            v[2 * p + 1] = __uint_as_float(hi);
        }
        float* dst = g_proj + ((size_t)n * W + l) * W + r0;
        *(float4*)dst       = make_float4(v[0], v[1], v[2], v[3]);
        *(float4*)(dst + 4) = make_float4(v[4], v[5], v[6], v[7]);
    }
}

// pack two fp32 into half2 (lo in low half, hi in high half): 1 instr (F2FP)
__device__ __forceinline__ unsigned pack_f16x2(float lo, float hi) {
    unsigned r;
    asm("cvt.rn.f16x2.f32 %0, %2, %1;" : "=r"(r) : "f"(lo), "f"(hi));
    return r;
}

// ---------------------------------------------------------------------------
// K1.5: build packed fp16 pair tables from g_proj.
// Block = one (group g, angle l); thread strides k. Layout puts each
// (group, 4-angle chunk) in one contiguous 32KB block for cp.async in K2.
// Global index: (((g*512 + l) * 2 + tab) * 512 + k).
// ---------------------------------------------------------------------------
__global__ __launch_bounds__(128) void k_pack() {
    const int bid = blockIdx.x;            // g*512 + l
    const int g = bid >> 9;
    const int l = bid & 511;
    const int t = threadIdx.x;
    const float* base = g_proj + ((size_t)g * 4) * W * W + (size_t)l * W;
#pragma unroll
    for (int s = 0; s < 4; ++s) {
        int k  = t + s * 128;
        int kn = (k < W - 1) ? (k + 1) : k;      // k=511 -> d=0
        float p0 = base[k];
        float p1 = base[k +     W * W];
        float p2 = base[k + 2 * W * W];
        float p3 = base[k + 3 * W * W];
        float d0 = base[kn]             - p0;
        float d1 = base[kn +     W * W] - p1;
        float d2 = base[kn + 2 * W * W] - p2;
        float d3 = base[kn + 3 * W * W] - p3;
        g_pairs[((size_t)bid * 2 + 0) * 512 + k] =
            make_uint2(pack_f16x2(p0, p1), pack_f16x2(d0, d1));
        g_pairs[((size_t)bid * 2 + 1) * 512 + k] =
            make_uint2(pack_f16x2(p2, p3), pack_f16x2(d2, d3));
    }
}

// ---------------------------------------------------------------------------
// K2: backprojection, 4 images per block, triple-buffered cp.async pipeline.
// Block = 512 thr = 16 rows x 32 lanes; thread owns 8 pixels
// (j = chh*256 + lane + 32u) of 4 images. Pair tables arrive in smem via
// LDGSTS two chunks ahead; one barrier per chunk; no build math in-kernel.
// Lerp: one (index, frac) serves 4 images: 2x LDS.64 + 2x HFMA2 + 4x F2F/FADD.
// In-circle pixels have ry in (0,511) with margin >= 4.9e-4, so no clamps:
// the 2^20 magic's "& 0xFF8" extracts floor(ry)*8 AND wraps out-of-circle
// garbage in-bounds (those pixels are masked at the end).
// ---------------------------------------------------------------------------
__global__ __launch_bounds__(512, 2) void k_backproj(float* __restrict__ out) {
    extern __shared__ __align__(16) uint2 sm[];   // NBUF * CHUNK_U2
    const int tid  = threadIdx.x;
    const int rg   = blockIdx.x >> 1;       // row group (0..31)
    const int chh  = blockIdx.x & 1;        // column half
    const int n0   = blockIdx.y * 4;
    const int i    = rg * 16 + (tid >> 5);
    const int lane = tid & 31;
    const float STEP = 2.0f / 511.0f;
    const float ti   = fmaf((float)i, STEP, -1.0f);
    const float tj0  = fmaf((float)(chh * 256 + lane), STEP, -1.0f);
    const float UST0 = 32.0f * STEP;

    const char* gp = (const char*)(g_pairs + (size_t)blockIdx.y * CHUNKS * CHUNK_U2);
    const unsigned smbase = (unsigned)__cvta_generic_to_shared(sm);

    // issue one chunk's 32KB copy: 2048 x 16B, 4 ops/thread
#define ISSUE(lc_)                                                          \
    do {                                                                    \
        const int _lc = (lc_);                                              \
        const unsigned _dst = smbase + (unsigned)(_lc % NBUF) * (CHUNK_U2 * 8); \
        const char* _src = gp + (size_t)_lc * (CHUNK_U2 * 8);               \
        _Pragma("unroll")                                                   \
        for (int _s = 0; _s < 4; ++_s) {                                    \
            unsigned _o = (unsigned)(tid + _s * 512) * 16u;                 \
            asm volatile("cp.async.cg.shared.global [%0], [%1], 16;"        \
                         :: "r"(_dst + _o), "l"(_src + _o));                \
        }                                                                   \
        asm volatile("cp.async.commit_group;");                             \
    } while (0)

    ISSUE(0);
    ISSUE(1);

    float acc[4][8];
#pragma unroll
    for (int m = 0; m < 4; ++m)
#pragma unroll
        for (int u = 0; u < 8; ++u) acc[m][u] = 0.0f;

    for (int lc = 0; lc < CHUNKS; ++lc) {
        if (lc < CHUNKS - 2) asm volatile("cp.async.wait_group 1;");
        else                 asm volatile("cp.async.wait_group 0;");
        __syncthreads();

        const char* cbase = (const char*)sm + (lc % NBUF) * (CHUNK_U2 * 8);
        const float4 csA = *(const float4*)&g_cs[lc * CH];      // c0,s0,c1,s1
        const float4 csB = *(const float4*)&g_cs[lc * CH + 2];  // c2,s2,c3,s3

#pragma unroll
        for (int a = 0; a < CH; ++a) {
            const float cB = (a == 0) ? csA.x : (a == 1) ? csA.z : (a == 2) ? csB.x : csB.z;
            const float sB = (a == 0) ? csA.y : (a == 1) ? csA.w : (a == 2) ? csB.y : csB.w;
            const float rowB = fmaf(-ti, sB, 255.5f);
            const float ry0  = fmaf(tj0, cB, rowB);
            const float ust  = cB * UST0;
            const char* PA = cbase + a * 8192;        // tab 0
            const char* PB = PA + 4096;               // tab 1
#pragma unroll
            for (int u = 0; u < 8; ++u) {
                float ry = fmaf((float)u, ust, ry0);
                float b20, b23;
                asm("add.rm.f32 %0, %1, 0f49800000;" : "=f"(b20) : "f"(ry)); // +2^20
                asm("add.rm.f32 %0, %1, 0f4B000000;" : "=f"(b23) : "f"(ry)); // +2^23
                unsigned off = __float_as_uint(b20) & 0xFF8u;   // 8*floor(ry), wraps
                float fl   = b23 - 8388608.0f;                  // floor(ry)
                float frac = ry - fl;
                unsigned fr2 = pack_f16x2(frac, frac);
                uint2 wA = *(const uint2*)(PA + off);
                uint2 wB = *(const uint2*)(PB + off);
                __half2 hf  = *reinterpret_cast<__half2*>(&fr2);
                __half2 v01 = __hfma2(hf, *reinterpret_cast<__half2*>(&wA.y),
                                          *reinterpret_cast<__half2*>(&wA.x));
                __half2 v23 = __hfma2(hf, *reinterpret_cast<__half2*>(&wB.y),
                                          *reinterpret_cast<__half2*>(&wB.x));
                acc[0][u] += __low2float(v01);
                acc[1][u] += __high2float(v01);
                acc[2][u] += __low2float(v23);
                acc[3][u] += __high2float(v23);
            }
        }

        if (lc + 2 < CHUNKS) ISSUE(lc + 2);   // buffer reuse safe: barrier above
                                              // proves all warps finished lc-1
    }
#undef ISSUE

    const float scale = (float)(3.14159265358979323846 / 1024.0); // pi/(2L)
    const float ti2 = ti * ti;
#pragma unroll
    for (int u = 0; u < 8; ++u) {
        int j = chh * 256 + lane + 32 * u;
        float tj = fmaf((float)j, STEP, -1.0f);
        bool in = (ti2 + tj * tj <= 1.0f);
        float* po = out + ((size_t)n0 * W + i) * W + j;
#pragma unroll
        for (int m = 0; m < 4; ++m)
            po[(size_t)m * W * W] = in ? acc[m][u] * scale : 0.0f;
    }
}

extern "C" void kernel_launch(void* const* d_in, const int* in_sizes, int n_in,
                              void* d_out, int out_size) {
    const float* x     = (const float*)d_in[0];
    const float* theta = (const float*)d_in[1];
    if (n_in >= 2 && in_sizes[0] == W && in_sizes[1] != W) { // defensive order swap
        x = (const float*)d_in[1];
        theta = (const float*)d_in[0];
    }
    float* out = (float*)d_out;

    const int smbytes = NBUF * CHUNK_U2 * 8;   // 96 KB dynamic smem
    cudaFuncSetAttribute(k_backproj, cudaFuncAttributeMaxDynamicSharedMemorySize,
                         smbytes);

    k_hh<<<1024, 256>>>();
    k_trig<<<1, 512>>>(theta);

    dim3 g1(4, 4, NIMG);
    k_filter<<<g1, 256>>>(x);

    k_pack<<<NGRP * W, 128>>>();

    dim3 g2(64, NGRP);
    k_backproj<<<g2, 512, smbytes>>>(out);
}

// round 13
// speedup vs baseline: 1.4783x; 1.1008x over previous
#include <cuda_runtime.h>
#include <cuda_fp16.h>

#define W      512
#define NIMG   32
#define CH     4
#define NGRP   (NIMG / 8)      // 4 image groups of 8
#define CHUNKS (W / CH)        // 128 angle chunks
#define CHUNK_BYTES 65536      // 4 angles x 4 tabs x 512 entries x 8B
#define CHUNK_U2    8192
#define NBUF   3

// Scratch: filtered projections transposed to [n][angle][r]
__device__ __align__(16) float g_proj[(size_t)NIMG * W * W];
// Packed fp16 pair tables: [group][chunk][angle-in-chunk][tab][k]
//   tab t: {h2(p_img2t, p_img2t+1), h2(d_img2t, d_img2t+1)}
__device__ __align__(16) uint2 g_pairs[(size_t)NGRP * CHUNKS * CHUNK_U2];
// Ramp-filter spatial taps, rearranged: g_hh[i] = h[(i-511) mod 1024]
__device__ float g_hh[1024];
// Per-angle (cos*255.5, sin*255.5)
__device__ float2 g_cs[W];

// ---------------------------------------------------------------------------
// K0: taps. h[m] = (1/1024) * sum_k filt[k] * cos(2*pi*k*m/1024),
// filt[k] = min(k,1024-k)/512. One block per tap, 256-thread double reduction.
// ---------------------------------------------------------------------------
__global__ __launch_bounds__(256) void k_hh() {
    __shared__ double red[256];
    const int i = blockIdx.x;
    const int t = threadIdx.x;
    if (i == 1023) { if (t == 0) g_hh[1023] = 0.0f; return; }
    const int m2 = (i + 513) & 1023;              // (i-511) mod 1024
    double s = 0.0;
    for (int k = t; k < 1024; k += 256) {
        int mn = (k < 512) ? k : (1024 - k);
        float f = (float)mn * (1.0f / 512.0f);    // filt[k]
        int ph = (k * m2) & 1023;                 // exact integer phase
        s += (double)f * (double)cospif((float)ph * (1.0f / 512.0f));
    }
    red[t] = s;
    __syncthreads();
    for (int st = 128; st > 0; st >>= 1) {
        if (t < st) red[t] += red[t + st];
        __syncthreads();
    }
    if (t == 0) g_hh[i] = (float)(red[0] / 1024.0);
}

__global__ void k_trig(const float* __restrict__ theta) {
    int l = threadIdx.x;
    if (l < W) {
        float frac = theta[l] * (1.0f / 180.0f);
        g_cs[l] = make_float2(cospif(frac) * 255.5f, sinpif(frac) * 255.5f);
    }
}

// ---------------------------------------------------------------------------
// K1: ramp filter as Toeplitz GEMM, output transposed:
//   g_proj[n][l][r] = sum_{m=0}^{511} x[n][m][l] * hh[r - m + 511]
// 256 threads, tile 128 l x 128 r, micro-tile 8l x 8r, packed fma.rn.f32x2.
// ---------------------------------------------------------------------------
__global__ __launch_bounds__(256) void k_filter(const float* __restrict__ x) {
    __shared__ __align__(16) float2 hh2[1023];  // hh2[i] = (hh[i], hh[i+1])
    __shared__ __align__(16) float  As[16][128];
    const int tid = threadIdx.x;
    const int n     = blockIdx.z;
    const int rBase = blockIdx.x * 128;
    const int lBase = blockIdx.y * 128;

    for (int i = tid; i < 1023; i += 256)
        hh2[i] = make_float2(g_hh[i], g_hh[i + 1]);

    const int tx = tid & 15;          // l lane (strided by 16)
    const int ty = tid >> 4;          // r group (8 consecutive r)
    const int r0 = rBase + ty * 8;

    unsigned long long acc[8][4];     // [sl][pair]: pair p = (r0+2p, r0+2p+1)
#pragma unroll
    for (int sl = 0; sl < 8; ++sl)
#pragma unroll
        for (int p = 0; p < 4; ++p) acc[sl][p] = 0ull;

    const float* xn = x + (size_t)n * W * W;
    const int lrow = tid >> 5;        // 0..7
    const int c4   = (tid & 31) << 2; // 0..124

    for (int mc = 0; mc < 32; ++mc) {
        __syncthreads();
        const float* src = xn + (size_t)(mc * 16) * W + lBase;
        *(float4*)&As[lrow][c4]     = *(const float4*)(src + (size_t)lrow * W + c4);
        *(float4*)&As[lrow + 8][c4] = *(const float4*)(src + (size_t)(lrow + 8) * W + c4);
        __syncthreads();
#pragma unroll
        for (int mm = 0; mm < 16; ++mm) {
            const int hb = 511 + r0 - (mc * 16 + mm);
            unsigned long long h2[4];
#pragma unroll
            for (int p = 0; p < 4; ++p)
                h2[p] = *(const unsigned long long*)(&hh2[hb + 2 * p]);
#pragma unroll
            for (int sl = 0; sl < 8; ++sl) {
                float a = As[mm][tx + 16 * sl];
                unsigned long long a2;
                asm("mov.b64 %0, {%1, %1};" : "=l"(a2) : "r"(__float_as_uint(a)));
#pragma unroll
                for (int p = 0; p < 4; ++p)
                    asm("fma.rn.f32x2 %0, %1, %2, %0;"
                        : "+l"(acc[sl][p]) : "l"(a2), "l"(h2[p]));
            }
        }
    }

#pragma unroll
    for (int sl = 0; sl < 8; ++sl) {
        const int l = lBase + tx + 16 * sl;
        float v[8];
#pragma unroll
        for (int p = 0; p < 4; ++p) {
            unsigned int lo, hi;
            asm("mov.b64 {%0, %1}, %2;" : "=r"(lo), "=r"(hi) : "l"(acc[sl][p]));
            v[2 * p]     = __uint_as_float(lo);
            v[2 * p + 1] = __uint_as_float(hi);
        }
        float* dst = g_proj + ((size_t)n * W + l) * W + r0;
        *(float4*)dst       = make_float4(v[0], v[1], v[2], v[3]);
        *(float4*)(dst + 4) = make_float4(v[4], v[5], v[6], v[7]);
    }
}

// pack two fp32 into half2 (lo in low half, hi in high half): 1 instr (F2FP)
__device__ __forceinline__ unsigned pack_f16x2(float lo, float hi) {
    unsigned r;
    asm("cvt.rn.f16x2.f32 %0, %2, %1;" : "=r"(r) : "f"(lo), "f"(hi));
    return r;
}

// ---------------------------------------------------------------------------
// K1.5: build packed fp16 pair tables from g_proj for 8-image groups.
// Block = one (group g, angle l); thread strides k. Layout keeps each
// (group, 4-angle chunk) contiguous (64KB) for cp.async in K2:
//   g_pairs[(((g*512 + l) * 4) + tab) * 512 + k], tab = image pair.
// ---------------------------------------------------------------------------
__global__ __launch_bounds__(128) void k_pack() {
    const int bid = blockIdx.x;            // g*512 + l
    const int g = bid >> 9;
    const int l = bid & 511;
    const int t = threadIdx.x;
    const float* base = g_proj + ((size_t)g * 8) * W * W + (size_t)l * W;
#pragma unroll
    for (int s = 0; s < 4; ++s) {
        int k  = t + s * 128;
        int kn = (k < W - 1) ? (k + 1) : k;      // k=511 -> d=0
        float p[8], d[8];
#pragma unroll
        for (int m = 0; m < 8; ++m) {
            p[m] = base[k  + (size_t)m * W * W];
            d[m] = base[kn + (size_t)m * W * W] - p[m];
        }
#pragma unroll
        for (int tab = 0; tab < 4; ++tab) {
            g_pairs[(((size_t)bid * 4) + tab) * 512 + k] =
                make_uint2(pack_f16x2(p[2 * tab], p[2 * tab + 1]),
                           pack_f16x2(d[2 * tab], d[2 * tab + 1]));
        }
    }
}

// ---------------------------------------------------------------------------
// K2: backprojection, 8 images per block, triple-buffered cp.async pipeline.
// Block = 512 thr = 16 rows x 32 lanes; thread owns 8 pixels
// (j = chh*256 + lane + 32u) of 8 images. One (index, frac) per
// (pixel, angle) feeds 4 tab lookups (4x LDS.64, 8B stride: conflict-free)
// + 4 HFMA2 + 8 fp32 accumulates.
// Index via single 2^23 magic: mantissa of (ry + 2^23) IS floor(ry);
// "& 0x1FF" keeps in-circle values exact (floor in [0,511]) and wraps
// out-of-circle garbage in-bounds (those pixels are masked at the end).
// frac = ry - (b23 - 2^23) is in [0,1) always; all values finite.
// ---------------------------------------------------------------------------
__global__ __launch_bounds__(512, 1) void k_backproj(float* __restrict__ out) {
    extern __shared__ __align__(16) char sm[];   // NBUF * CHUNK_BYTES
    const int tid  = threadIdx.x;
    const int rg   = blockIdx.x >> 1;       // row group (0..31)
    const int chh  = blockIdx.x & 1;        // column half
    const int n0   = blockIdx.y * 8;
    const int i    = rg * 16 + (tid >> 5);
    const int lane = tid & 31;
    const float STEP = 2.0f / 511.0f;
    const float ti   = fmaf((float)i, STEP, -1.0f);
    const float tj0  = fmaf((float)(chh * 256 + lane), STEP, -1.0f);
    const float UST0 = 32.0f * STEP;

    const char* gp = (const char*)(g_pairs + (size_t)blockIdx.y * CHUNKS * CHUNK_U2);
    const unsigned smbase = (unsigned)__cvta_generic_to_shared(sm);

    // issue one chunk's 64KB copy: 4096 x 16B, 8 ops/thread
#define ISSUE(lc_)                                                          \
    do {                                                                    \
        const int _lc = (lc_);                                              \
        const unsigned _dst = smbase + (unsigned)(_lc % NBUF) * CHUNK_BYTES; \
        const char* _src = gp + (size_t)_lc * CHUNK_BYTES;                  \
        _Pragma("unroll")                                                   \
        for (int _s = 0; _s < 8; ++_s) {                                    \
            unsigned _o = (unsigned)(tid + _s * 512) * 16u;                 \
            asm volatile("cp.async.cg.shared.global [%0], [%1], 16;"        \
                         :: "r"(_dst + _o), "l"(_src + _o));                \
        }                                                                   \
        asm volatile("cp.async.commit_group;");                             \
    } while (0)

    ISSUE(0);
    ISSUE(1);

    float acc[8][8];                         // [image][u]
#pragma unroll
    for (int m = 0; m < 8; ++m)
#pragma unroll
        for (int u = 0; u < 8; ++u) acc[m][u] = 0.0f;

    for (int lc = 0; lc < CHUNKS; ++lc) {
        if (lc < CHUNKS - 2) asm volatile("cp.async.wait_group 1;");
        else                 asm volatile("cp.async.wait_group 0;");
        __syncthreads();

        const char* cbase = sm + (lc % NBUF) * CHUNK_BYTES;
        const float4 csA = *(const float4*)&g_cs[lc * CH];      // c0,s0,c1,s1
        const float4 csB = *(const float4*)&g_cs[lc * CH + 2];  // c2,s2,c3,s3

#pragma unroll
        for (int a = 0; a < CH; ++a) {
            const float cB = (a == 0) ? csA.x : (a == 1) ? csA.z : (a == 2) ? csB.x : csB.z;
            const float sB = (a == 0) ? csA.y : (a == 1) ? csA.w : (a == 2) ? csB.y : csB.w;
            const float rowB = fmaf(-ti, sB, 255.5f);
            const float ry0  = fmaf(tj0, cB, rowB);
            const float ust  = cB * UST0;
            const char* Pa = cbase + a * 16384;   // 4 tabs of 4KB follow
#pragma unroll
            for (int u = 0; u < 8; ++u) {
                float ry = fmaf((float)u, ust, ry0);
                float b23;
                asm("add.rm.f32 %0, %1, 0f4B000000;" : "=f"(b23) : "f"(ry)); // +2^23
                unsigned idx = __float_as_uint(b23) & 0x1FFu;   // floor(ry), wraps
                float fl   = b23 - 8388608.0f;                  // floor(ry)
                float frac = ry - fl;
                unsigned fr2 = pack_f16x2(frac, frac);
                const char* e = Pa + idx * 8u;
                uint2 w0 = *(const uint2*)(e);
                uint2 w1 = *(const uint2*)(e + 4096);
                uint2 w2 = *(const uint2*)(e + 8192);
                uint2 w3 = *(const uint2*)(e + 12288);
                __half2 hf = *reinterpret_cast<__half2*>(&fr2);
                __half2 v0 = __hfma2(hf, *reinterpret_cast<__half2*>(&w0.y),
                                         *reinterpret_cast<__half2*>(&w0.x));
                __half2 v1 = __hfma2(hf, *reinterpret_cast<__half2*>(&w1.y),
                                         *reinterpret_cast<__half2*>(&w1.x));
                __half2 v2 = __hfma2(hf, *reinterpret_cast<__half2*>(&w2.y),
                                         *reinterpret_cast<__half2*>(&w2.x));
                __half2 v3 = __hfma2(hf, *reinterpret_cast<__half2*>(&w3.y),
                                         *reinterpret_cast<__half2*>(&w3.x));
                acc[0][u] += __low2float(v0);  acc[1][u] += __high2float(v0);
                acc[2][u] += __low2float(v1);  acc[3][u] += __high2float(v1);
                acc[4][u] += __low2float(v2);  acc[5][u] += __high2float(v2);
                acc[6][u] += __low2float(v3);  acc[7][u] += __high2float(v3);
            }
        }

        if (lc + 2 < CHUNKS) ISSUE(lc + 2);   // safe: barrier above proves all
                                              // warps finished buffer lc-1
    }
#undef ISSUE

    const float scale = (float)(3.14159265358979323846 / 1024.0); // pi/(2L)
    const float ti2 = ti * ti;
#pragma unroll
    for (int u = 0; u < 8; ++u) {
        int j = chh * 256 + lane + 32 * u;
        float tj = fmaf((float)j, STEP, -1.0f);
        bool in = (ti2 + tj * tj <= 1.0f);
        float* po = out + ((size_t)n0 * W + i) * W + j;
#pragma unroll
        for (int m = 0; m < 8; ++m)
            po[(size_t)m * W * W] = in ? acc[m][u] * scale : 0.0f;
    }
}

extern "C" void kernel_launch(void* const* d_in, const int* in_sizes, int n_in,
                              void* d_out, int out_size) {
    const float* x     = (const float*)d_in[0];
    const float* theta = (const float*)d_in[1];
    if (n_in >= 2 && in_sizes[0] == W && in_sizes[1] != W) { // defensive order swap
        x = (const float*)d_in[1];
        theta = (const float*)d_in[0];
    }
    float* out = (float*)d_out;

    const int smbytes = NBUF * CHUNK_BYTES;   // 192 KB dynamic smem
    cudaFuncSetAttribute(k_backproj, cudaFuncAttributeMaxDynamicSharedMemorySize,
                         smbytes);

    k_hh<<<1024, 256>>>();
    k_trig<<<1, 512>>>(theta);

    dim3 g1(4, 4, NIMG);
    k_filter<<<g1, 256>>>(x);

    k_pack<<<NGRP * W, 128>>>();

    dim3 g2(64, NGRP);
    k_backproj<<<g2, 512, smbytes>>>(out);
}

// round 14
// speedup vs baseline: 1.6287x; 1.1017x over previous
#include <cuda_runtime.h>
#include <cuda_fp16.h>

#define W      512
#define NIMG   32
#define CH     4
#define NGRP   (NIMG / 8)      // 4 image groups of 8
#define CHUNKS (W / CH)        // 128 angle chunks
#define CHUNK_BYTES 65536      // 4 angles x 2 tabs x 512 entries x 16B
#define NBUF   3

// Scratch: filtered projections transposed to [n][angle][r]
__device__ __align__(16) float g_proj[(size_t)NIMG * W * W];
// Packed fp16 quad tables: [group][angle l][tab][k], 16B entries:
//   tab t entry: {h2(p_a,p_b), h2(d_a,d_b), h2(p_c,p_d), h2(d_c,d_d)}
//   tab 0 -> imgs 0..3, tab 1 -> imgs 4..7 of the group.
__device__ __align__(16) uint4 g_pairs[(size_t)NGRP * W * 2 * 512];
// Ramp-filter spatial taps, rearranged: g_hh[i] = h[(i-511) mod 1024]
__device__ float g_hh[1024];
// Per-angle (cos*255.5, sin*255.5)
__device__ float2 g_cs[W];

// ---------------------------------------------------------------------------
// K0: taps. h[m] = (1/1024) * sum_k filt[k] * cos(2*pi*k*m/1024),
// filt[k] = min(k,1024-k)/512. One block per tap, 256-thread double reduction.
// ---------------------------------------------------------------------------
__global__ __launch_bounds__(256) void k_hh() {
    __shared__ double red[256];
    const int i = blockIdx.x;
    const int t = threadIdx.x;
    if (i == 1023) { if (t == 0) g_hh[1023] = 0.0f; return; }
    const int m2 = (i + 513) & 1023;              // (i-511) mod 1024
    double s = 0.0;
    for (int k = t; k < 1024; k += 256) {
        int mn = (k < 512) ? k : (1024 - k);
        float f = (float)mn * (1.0f / 512.0f);    // filt[k]
        int ph = (k * m2) & 1023;                 // exact integer phase
        s += (double)f * (double)cospif((float)ph * (1.0f / 512.0f));
    }
    red[t] = s;
    __syncthreads();
    for (int st = 128; st > 0; st >>= 1) {
        if (t < st) red[t] += red[t + st];
        __syncthreads();
    }
    if (t == 0) g_hh[i] = (float)(red[0] / 1024.0);
}

__global__ void k_trig(const float* __restrict__ theta) {
    int l = threadIdx.x;
    if (l < W) {
        float frac = theta[l] * (1.0f / 180.0f);
        g_cs[l] = make_float2(cospif(frac) * 255.5f, sinpif(frac) * 255.5f);
    }
}

// ---------------------------------------------------------------------------
// K1: ramp filter as Toeplitz GEMM, output transposed:
//   g_proj[n][l][r] = sum_{m=0}^{511} x[n][m][l] * hh[r - m + 511]
// 256 threads, tile 128 l x 128 r, micro-tile 8l x 8r, packed fma.rn.f32x2.
// ---------------------------------------------------------------------------
__global__ __launch_bounds__(256) void k_filter(const float* __restrict__ x) {
    __shared__ __align__(16) float2 hh2[1023];  // hh2[i] = (hh[i], hh[i+1])
    __shared__ __align__(16) float  As[16][128];
    const int tid = threadIdx.x;
    const int n     = blockIdx.z;
    const int rBase = blockIdx.x * 128;
    const int lBase = blockIdx.y * 128;

    for (int i = tid; i < 1023; i += 256)
        hh2[i] = make_float2(g_hh[i], g_hh[i + 1]);

    const int tx = tid & 15;          // l lane (strided by 16)
    const int ty = tid >> 4;          // r group (8 consecutive r)
    const int r0 = rBase + ty * 8;

    unsigned long long acc[8][4];     // [sl][pair]: pair p = (r0+2p, r0+2p+1)
#pragma unroll
    for (int sl = 0; sl < 8; ++sl)
#pragma unroll
        for (int p = 0; p < 4; ++p) acc[sl][p] = 0ull;

    const float* xn = x + (size_t)n * W * W;
    const int lrow = tid >> 5;        // 0..7
    const int c4   = (tid & 31) << 2; // 0..124

    for (int mc = 0; mc < 32; ++mc) {
        __syncthreads();
        const float* src = xn + (size_t)(mc * 16) * W + lBase;
        *(float4*)&As[lrow][c4]     = *(const float4*)(src + (size_t)lrow * W + c4);
        *(float4*)&As[lrow + 8][c4] = *(const float4*)(src + (size_t)(lrow + 8) * W + c4);
        __syncthreads();
#pragma unroll
        for (int mm = 0; mm < 16; ++mm) {
            const int hb = 511 + r0 - (mc * 16 + mm);
            unsigned long long h2[4];
#pragma unroll
            for (int p = 0; p < 4; ++p)
                h2[p] = *(const unsigned long long*)(&hh2[hb + 2 * p]);
#pragma unroll
            for (int sl = 0; sl < 8; ++sl) {
                float a = As[mm][tx + 16 * sl];
                unsigned long long a2;
                asm("mov.b64 %0, {%1, %1};" : "=l"(a2) : "r"(__float_as_uint(a)));
#pragma unroll
                for (int p = 0; p < 4; ++p)
                    asm("fma.rn.f32x2 %0, %1, %2, %0;"
                        : "+l"(acc[sl][p]) : "l"(a2), "l"(h2[p]));
            }
        }
    }

#pragma unroll
    for (int sl = 0; sl < 8; ++sl) {
        const int l = lBase + tx + 16 * sl;
        float v[8];
#pragma unroll
        for (int p = 0; p < 4; ++p) {
            unsigned int lo, hi;
            asm("mov.b64 {%0, %1}, %2;" : "=r"(lo), "=r"(hi) : "l"(acc[sl][p]));
            v[2 * p]     = __uint_as_float(lo);
            v[2 * p + 1] = __uint_as_float(hi);
        }
        float* dst = g_proj + ((size_t)n * W + l) * W + r0;
        *(float4*)dst       = make_float4(v[0], v[1], v[2], v[3]);
        *(float4*)(dst + 4) = make_float4(v[4], v[5], v[6], v[7]);
    }
}

// pack two fp32 into half2 (lo in low half, hi in high half): 1 instr (F2FP)
__device__ __forceinline__ unsigned pack_f16x2(float lo, float hi) {
    unsigned r;
    asm("cvt.rn.f16x2.f32 %0, %2, %1;" : "=r"(r) : "f"(lo), "f"(hi));
    return r;
}

// ---------------------------------------------------------------------------
// K1.5: build packed fp16 quad tables from g_proj for 8-image groups.
// Block = one (group g, angle l); thread strides k. Entry (16B) holds
// p/d pairs for 4 images so K2 fetches them with one LDS.128.
// Index: ((g*512 + l)*2 + tab)*512 + k  ->  each (g, 4-angle chunk) is one
// contiguous 64KB block for cp.async.
// ---------------------------------------------------------------------------
__global__ __launch_bounds__(128) void k_pack() {
    const int bid = blockIdx.x;            // g*512 + l
    const int g = bid >> 9;
    const int l = bid & 511;
    const int t = threadIdx.x;
    const float* base = g_proj + ((size_t)g * 8) * W * W + (size_t)l * W;
#pragma unroll
    for (int s = 0; s < 4; ++s) {
        int k  = t + s * 128;
        int kn = (k < W - 1) ? (k + 1) : k;      // k=511 -> d=0
        float p[8], d[8];
#pragma unroll
        for (int m = 0; m < 8; ++m) {
            p[m] = base[k  + (size_t)m * W * W];
            d[m] = base[kn + (size_t)m * W * W] - p[m];
        }
#pragma unroll
        for (int tab = 0; tab < 2; ++tab) {
            int m0 = tab * 4;
            g_pairs[(((size_t)bid * 2) + tab) * 512 + k] =
                make_uint4(pack_f16x2(p[m0 + 0], p[m0 + 1]),
                           pack_f16x2(d[m0 + 0], d[m0 + 1]),
                           pack_f16x2(p[m0 + 2], p[m0 + 3]),
                           pack_f16x2(d[m0 + 2], d[m0 + 3]));
        }
    }
}

__device__ __forceinline__ __half2 u2h2(unsigned v) {
    return *reinterpret_cast<__half2*>(&v);
}

// ---------------------------------------------------------------------------
// K2: backprojection, 8 images per block, triple-buffered cp.async pipeline.
// Block = 512 thr = 16 rows x 32 lanes; thread owns 8 pixels
// (j = chh*256 + lane + 32u) of 8 images. Angles processed in PAIRS:
// each angle's lerp stays fp16 (LDS.128 quad entry -> 2x HFMA2 per tab),
// the pair is merged with HADD2, and converted/accumulated to fp32 once
// per 2 angles (halves the F2F+FADD cost).
// Index via single 2^23 magic: mantissa of (ry + 2^23) IS floor(ry);
// "& 0x1FF" keeps in-circle values exact (floor in [0,511]) and wraps
// out-of-circle garbage in-bounds (those pixels are masked at the end).
// ---------------------------------------------------------------------------
__global__ __launch_bounds__(512, 1) void k_backproj(float* __restrict__ out) {
    extern __shared__ __align__(16) char sm[];   // NBUF * CHUNK_BYTES
    const int tid  = threadIdx.x;
    const int rg   = blockIdx.x >> 1;       // row group (0..31)
    const int chh  = blockIdx.x & 1;        // column half
    const int n0   = blockIdx.y * 8;
    const int i    = rg * 16 + (tid >> 5);
    const int lane = tid & 31;
    const float STEP = 2.0f / 511.0f;
    const float ti   = fmaf((float)i, STEP, -1.0f);
    const float tj0  = fmaf((float)(chh * 256 + lane), STEP, -1.0f);
    const float UST0 = 32.0f * STEP;

    const char* gp = (const char*)g_pairs + (size_t)blockIdx.y * CHUNKS * CHUNK_BYTES;
    const unsigned smbase = (unsigned)__cvta_generic_to_shared(sm);

    // issue one chunk's 64KB copy: 4096 x 16B, 8 ops/thread
#define ISSUE(lc_)                                                          \
    do {                                                                    \
        const int _lc = (lc_);                                              \
        const unsigned _dst = smbase + (unsigned)(_lc % NBUF) * CHUNK_BYTES; \
        const char* _src = gp + (size_t)_lc * CHUNK_BYTES;                  \
        _Pragma("unroll")                                                   \
        for (int _s = 0; _s < 8; ++_s) {                                    \
            unsigned _o = (unsigned)(tid + _s * 512) * 16u;                 \
            asm volatile("cp.async.cg.shared.global [%0], [%1], 16;"        \
                         :: "r"(_dst + _o), "l"(_src + _o));                \
        }                                                                   \
        asm volatile("cp.async.commit_group;");                             \
    } while (0)

    ISSUE(0);
    ISSUE(1);

    float acc[8][8];                         // [image][u]
#pragma unroll
    for (int m = 0; m < 8; ++m)
#pragma unroll
        for (int u = 0; u < 8; ++u) acc[m][u] = 0.0f;

    for (int lc = 0; lc < CHUNKS; ++lc) {
        if (lc < CHUNKS - 2) asm volatile("cp.async.wait_group 1;");
        else                 asm volatile("cp.async.wait_group 0;");
        __syncthreads();

        const char* cbase = sm + (lc % NBUF) * CHUNK_BYTES;
        const float4 csA = *(const float4*)&g_cs[lc * CH];      // c0,s0,c1,s1
        const float4 csB = *(const float4*)&g_cs[lc * CH + 2];  // c2,s2,c3,s3

#pragma unroll
        for (int ap = 0; ap < 2; ++ap) {      // angle pair (2*ap, 2*ap+1)
            const float cE = (ap == 0) ? csA.x : csB.x;
            const float sE = (ap == 0) ? csA.y : csB.y;
            const float cO = (ap == 0) ? csA.z : csB.z;
            const float sO = (ap == 0) ? csA.w : csB.w;
            const float rowE = fmaf(-ti, sE, 255.5f);
            const float rowO = fmaf(-ti, sO, 255.5f);
            const float ry0E = fmaf(tj0, cE, rowE);
            const float ry0O = fmaf(tj0, cO, rowO);
            const float ustE = cE * UST0;
            const float ustO = cO * UST0;
            const char* PE = cbase + (2 * ap)     * 16384;  // tab0; tab1 at +8192
            const char* PO = cbase + (2 * ap + 1) * 16384;
#pragma unroll
            for (int u = 0; u < 8; ++u) {
                // even angle
                float ryE = fmaf((float)u, ustE, ry0E);
                float bE;
                asm("add.rm.f32 %0, %1, 0f4B000000;" : "=f"(bE) : "f"(ryE));
                unsigned offE = (__float_as_uint(bE) & 0x1FFu) * 16u;
                float frE = ryE - (bE - 8388608.0f);
                __half2 hfE = u2h2(pack_f16x2(frE, frE));
                uint4 ea = *(const uint4*)(PE + offE);
                uint4 eb = *(const uint4*)(PE + 8192 + offE);
                __half2 e0 = __hfma2(hfE, u2h2(ea.y), u2h2(ea.x));
                __half2 e1 = __hfma2(hfE, u2h2(ea.w), u2h2(ea.z));
                __half2 e2 = __hfma2(hfE, u2h2(eb.y), u2h2(eb.x));
                __half2 e3 = __hfma2(hfE, u2h2(eb.w), u2h2(eb.z));
                // odd angle
                float ryO = fmaf((float)u, ustO, ry0O);
                float bO;
                asm("add.rm.f32 %0, %1, 0f4B000000;" : "=f"(bO) : "f"(ryO));
                unsigned offO = (__float_as_uint(bO) & 0x1FFu) * 16u;
                float frO = ryO - (bO - 8388608.0f);
                __half2 hfO = u2h2(pack_f16x2(frO, frO));
                uint4 oa = *(const uint4*)(PO + offO);
                uint4 ob = *(const uint4*)(PO + 8192 + offO);
                __half2 m0 = __hadd2(e0, __hfma2(hfO, u2h2(oa.y), u2h2(oa.x)));
                __half2 m1 = __hadd2(e1, __hfma2(hfO, u2h2(oa.w), u2h2(oa.z)));
                __half2 m2 = __hadd2(e2, __hfma2(hfO, u2h2(ob.y), u2h2(ob.x)));
                __half2 m3 = __hadd2(e3, __hfma2(hfO, u2h2(ob.w), u2h2(ob.z)));
                acc[0][u] += __low2float(m0);  acc[1][u] += __high2float(m0);
                acc[2][u] += __low2float(m1);  acc[3][u] += __high2float(m1);
                acc[4][u] += __low2float(m2);  acc[5][u] += __high2float(m2);
                acc[6][u] += __low2float(m3);  acc[7][u] += __high2float(m3);
            }
        }

        if (lc + 2 < CHUNKS) ISSUE(lc + 2);   // safe: barrier above proves all
                                              // warps finished buffer lc-1
    }
#undef ISSUE

    const float scale = (float)(3.14159265358979323846 / 1024.0); // pi/(2L)
    const float ti2 = ti * ti;
#pragma unroll
    for (int u = 0; u < 8; ++u) {
        int j = chh * 256 + lane + 32 * u;
        float tj = fmaf((float)j, STEP, -1.0f);
        bool in = (ti2 + tj * tj <= 1.0f);
        float* po = out + ((size_t)n0 * W + i) * W + j;
#pragma unroll
        for (int m = 0; m < 8; ++m)
            po[(size_t)m * W * W] = in ? acc[m][u] * scale : 0.0f;
    }
}

extern "C" void kernel_launch(void* const* d_in, const int* in_sizes, int n_in,
                              void* d_out, int out_size) {
    const float* x     = (const float*)d_in[0];
    const float* theta = (const float*)d_in[1];
    if (n_in >= 2 && in_sizes[0] == W && in_sizes[1] != W) { // defensive order swap
        x = (const float*)d_in[1];
        theta = (const float*)d_in[0];
    }
    float* out = (float*)d_out;

    const int smbytes = NBUF * CHUNK_BYTES;   // 192 KB dynamic smem
    cudaFuncSetAttribute(k_backproj, cudaFuncAttributeMaxDynamicSharedMemorySize,
                         smbytes);

    k_hh<<<1024, 256>>>();
    k_trig<<<1, 512>>>(theta);

    dim3 g1(4, 4, NIMG);
    k_filter<<<g1, 256>>>(x);

    k_pack<<<NGRP * W, 128>>>();

    dim3 g2(64, NGRP);
    k_backproj<<<g2, 512, smbytes>>>(out);
}